// round 2
// baseline (speedup 1.0000x reference)
#include <cuda_runtime.h>
#include <math.h>

#define Bz 32
#define Sz 512
#define Ez 256
#define Uz 1024
#define U2 2048
#define BSz (Bz*Sz)   // 16384

#define NBLK 128
#define NTHR 256

// -------- scratch (device globals; no allocation allowed) --------
__device__ float g_Xg[(size_t)BSz * U2];  // x-part gate preact + bias
__device__ float g_Xc[(size_t)BSz * Uz];  // x-part cand preact + bias
__device__ float g_y0[(size_t)BSz * Uz];  // layer0 outputs
__device__ float g_h [Bz * Uz];
__device__ float g_u [Bz * Uz];
__device__ float g_a [Bz * Uz];           // r*h

// grid barrier state (zero-initialized at module load; self-resetting)
__device__ unsigned int g_count = 0;
__device__ volatile unsigned int g_gen = 0;

__device__ __forceinline__ void gsync() {
    __syncthreads();
    if (threadIdx.x == 0) {
        __threadfence();
        unsigned int gen = g_gen;
        if (atomicAdd(&g_count, 1u) == NBLK - 1u) {
            g_count = 0;
            __threadfence();
            g_gen = gen + 1u;
        } else {
            while (g_gen == gen) { __nanosleep(64); }
        }
        __threadfence();
    }
    __syncthreads();
}

// ------------------------------------------------------------------
// C[M,N] = A @ W + bias.   A row m: (xidx ? Abase + xidx[m]*K : Abase + m*K)
__global__ __launch_bounds__(256) void sgemm_bias(
    const float* __restrict__ Abase, const int* __restrict__ xidx,
    const float* __restrict__ W, const float* __restrict__ bias,
    float* __restrict__ C, int M, int N, int K)
{
    __shared__ float As[8][128];
    __shared__ float Bs[8][128];

    int tid = threadIdx.x;
    int ty = tid >> 4;
    int tx = tid & 15;
    int rowBase = blockIdx.y * 128;
    int colBase = blockIdx.x * 128;

    int arow  = tid >> 1;
    int acol4 = (tid & 1) * 4;
    int am = rowBase + arow;
    const float* arowptr;
    if (xidx) arowptr = Abase + (size_t)xidx[am] * K;
    else      arowptr = Abase + (size_t)am * K;

    int brow  = tid >> 5;
    int bcol4 = (tid & 31) * 4;

    float acc[8][8];
#pragma unroll
    for (int i = 0; i < 8; i++)
#pragma unroll
        for (int j = 0; j < 8; j++) acc[i][j] = 0.f;

    for (int k0 = 0; k0 < K; k0 += 8) {
        float4 av = *(const float4*)&arowptr[k0 + acol4];
        As[acol4 + 0][arow] = av.x;
        As[acol4 + 1][arow] = av.y;
        As[acol4 + 2][arow] = av.z;
        As[acol4 + 3][arow] = av.w;

        float4 bv = *(const float4*)&W[(size_t)(k0 + brow) * N + colBase + bcol4];
        *(float4*)&Bs[brow][bcol4] = bv;

        __syncthreads();
#pragma unroll
        for (int kk = 0; kk < 8; kk++) {
            float4 a0 = *(const float4*)&As[kk][ty * 8];
            float4 a1 = *(const float4*)&As[kk][ty * 8 + 4];
            float4 b0 = *(const float4*)&Bs[kk][tx * 8];
            float4 b1 = *(const float4*)&Bs[kk][tx * 8 + 4];
            float ar[8] = {a0.x,a0.y,a0.z,a0.w,a1.x,a1.y,a1.z,a1.w};
            float br[8] = {b0.x,b0.y,b0.z,b0.w,b1.x,b1.y,b1.z,b1.w};
#pragma unroll
            for (int i = 0; i < 8; i++)
#pragma unroll
                for (int j = 0; j < 8; j++)
                    acc[i][j] = fmaf(ar[i], br[j], acc[i][j]);
        }
        __syncthreads();
    }

    int col0 = colBase + tx * 8;
    float4 bia0 = *(const float4*)&bias[col0];
    float4 bia1 = *(const float4*)&bias[col0 + 4];
#pragma unroll
    for (int i = 0; i < 8; i++) {
        int row = rowBase + ty * 8 + i;
        float4 v0, v1;
        v0.x = acc[i][0] + bia0.x; v0.y = acc[i][1] + bia0.y;
        v0.z = acc[i][2] + bia0.z; v0.w = acc[i][3] + bia0.w;
        v1.x = acc[i][4] + bia1.x; v1.y = acc[i][5] + bia1.y;
        v1.z = acc[i][6] + bia1.z; v1.w = acc[i][7] + bia1.w;
        *(float4*)&C[(size_t)row * N + col0]     = v0;
        *(float4*)&C[(size_t)row * N + col0 + 4] = v1;
    }
}

// ------------------------------------------------------------------
// Persistent GRU scan for one layer. 128 blocks x 256 threads.
// Block caches its W slices in SMEM once; loops over all 512 time steps
// with 2 software grid barriers per step.
//
// SMEM (floats): swg [1024][16]   = 16384   (gate W slice, cols jg0..jg0+15 of 2048)
//                swct[8][1028]    =  8224   (cand W slice transposed, pad->conflict-free)
//                sh  [32][132]    =  4224   (h / a k-tile, 128 wide)
#define SWG_F   16384
#define SWCT_F  8224
#define SH_F    4224
#define SMEM_FLOATS (SWG_F + SWCT_F + SH_F)

__global__ __launch_bounds__(NTHR) void gru_scan(
    const float* __restrict__ Wgh,   // [1024][2048] (h-part rows of Wg)
    const float* __restrict__ Wch,   // [1024][1024] (h-part rows of Wc)
    const float* __restrict__ Xg,    // [16384][2048]
    const float* __restrict__ Xc,    // [16384][1024]
    const float* __restrict__ h0,    // [32][1024]
    float* __restrict__ y,           // [16384][1024]
    float* __restrict__ s_out)       // [32][1024]
{
    extern __shared__ float sm[];
    float* swg  = sm;
    float* swct = sm + SWG_F;
    float* sh   = sm + SWG_F + SWCT_F;

    const int tid = threadIdx.x;
    const int blk = blockIdx.x;
    const int b   = tid >> 3;      // 0..31
    const int jj  = tid & 7;       // 0..7
    const int jg0 = blk * 16;      // gate-col base (of 2048)
    const int jc0 = blk * 8;       // cand-col base (of 1024)

    // ---- preload W slices into SMEM (once) ----
    for (int i = tid; i < 4096; i += NTHR) {            // swg: 4096 float4
        int k  = i >> 2;
        int c4 = (i & 3) * 4;
        float4 v = *(const float4*)&Wgh[(size_t)k * U2 + jg0 + c4];
        *(float4*)&swg[k * 16 + c4] = v;
    }
    for (int i = tid; i < 2048; i += NTHR) {            // swct: transpose 8 cols
        int k  = i >> 1;
        int j4 = (i & 1) * 4;
        float4 v = *(const float4*)&Wch[(size_t)k * Uz + jc0 + j4];
        swct[(j4 + 0) * 1028 + k] = v.x;
        swct[(j4 + 1) * 1028 + k] = v.y;
        swct[(j4 + 2) * 1028 + k] = v.z;
        swct[(j4 + 3) * 1028 + k] = v.w;
    }

    // ---- init h ----
    {
        int i = blk * NTHR + tid;       // exactly covers 32768
        __stcg(&g_h[i], h0[i]);
    }
    gsync();

    for (int t = 0; t < Sz; t++) {
        // ================= phase 1: gates =================
        float acc0 = 0.f, acc1 = 0.f;
        {
            float4 p[4];
#pragma unroll
            for (int r = 0; r < 4; r++) {
                int f4 = tid + r * NTHR;
                int row = f4 >> 5, c4 = (f4 & 31) * 4;
                p[r] = __ldcg((const float4*)&g_h[row * Uz + c4]);
            }
            for (int k0 = 0; k0 < Uz; k0 += 128) {
                __syncthreads();
#pragma unroll
                for (int r = 0; r < 4; r++) {
                    int f4 = tid + r * NTHR;
                    int row = f4 >> 5, c4 = (f4 & 31) * 4;
                    *(float4*)&sh[row * 132 + c4] = p[r];
                }
                __syncthreads();
                if (k0 + 128 < Uz) {
#pragma unroll
                    for (int r = 0; r < 4; r++) {
                        int f4 = tid + r * NTHR;
                        int row = f4 >> 5, c4 = (f4 & 31) * 4;
                        p[r] = __ldcg((const float4*)&g_h[row * Uz + k0 + 128 + c4]);
                    }
                }
#pragma unroll 16
                for (int kk = 0; kk < 128; kk++) {
                    float hv = sh[b * 132 + kk];
                    float2 w = *(const float2*)&swg[(k0 + kk) * 16 + (jj << 1)];
                    acc0 = fmaf(hv, w.x, acc0);
                    acc1 = fmaf(hv, w.y, acc1);
                }
            }
        }
        {
            int m  = b * Sz + t;
            int jg = jg0 + (jj << 1);
            float2 xg = *(const float2*)&Xg[(size_t)m * U2 + jg];
            float gi0 = xg.x + acc0;
            float gi1 = xg.y + acc1;
            float s0v = 1.f / (1.f + expf(-gi0));
            float s1v = 1.f / (1.f + expf(-gi1));
            if (jg < Uz) {   // r-half -> a = r*h
                float hv0 = __ldcg(&g_h[b * Uz + jg]);
                float hv1 = __ldcg(&g_h[b * Uz + jg + 1]);
                __stcg(&g_a[b * Uz + jg],     s0v * hv0);
                __stcg(&g_a[b * Uz + jg + 1], s1v * hv1);
            } else {         // u-half
                __stcg(&g_u[b * Uz + jg - Uz],     s0v);
                __stcg(&g_u[b * Uz + jg - Uz + 1], s1v);
            }
        }
        gsync();

        // ================= phase 2: candidate + update =================
        float acc = 0.f;
        {
            float4 p[4];
#pragma unroll
            for (int r = 0; r < 4; r++) {
                int f4 = tid + r * NTHR;
                int row = f4 >> 5, c4 = (f4 & 31) * 4;
                p[r] = __ldcg((const float4*)&g_a[row * Uz + c4]);
            }
            for (int k0 = 0; k0 < Uz; k0 += 128) {
                __syncthreads();
#pragma unroll
                for (int r = 0; r < 4; r++) {
                    int f4 = tid + r * NTHR;
                    int row = f4 >> 5, c4 = (f4 & 31) * 4;
                    *(float4*)&sh[row * 132 + c4] = p[r];
                }
                __syncthreads();
                if (k0 + 128 < Uz) {
#pragma unroll
                    for (int r = 0; r < 4; r++) {
                        int f4 = tid + r * NTHR;
                        int row = f4 >> 5, c4 = (f4 & 31) * 4;
                        p[r] = __ldcg((const float4*)&g_a[row * Uz + k0 + 128 + c4]);
                    }
                }
#pragma unroll 8
                for (int kk = 0; kk < 128; kk += 4) {
                    float4 av = *(const float4*)&sh[b * 132 + kk];
                    float4 wv = *(const float4*)&swct[jj * 1028 + k0 + kk];
                    acc = fmaf(av.x, wv.x, acc);
                    acc = fmaf(av.y, wv.y, acc);
                    acc = fmaf(av.z, wv.z, acc);
                    acc = fmaf(av.w, wv.w, acc);
                }
            }
        }
        {
            int m  = b * Sz + t;
            int jc = jc0 + jj;
            float c  = tanhf(Xc[(size_t)m * Uz + jc] + acc);
            float uu = __ldcg(&g_u[b * Uz + jc]);
            float ho = __ldcg(&g_h[b * Uz + jc]);
            float hn = uu * ho + (1.f - uu) * c;
            __stcg(&g_h[b * Uz + jc], hn);
            y[(size_t)m * Uz + jc] = hn;
        }
        gsync();
    }

    // ---- write final state ----
    {
        int i = blk * NTHR + tid;
        s_out[i] = __ldcg(&g_h[i]);
    }
}

// ------------------------------------------------------------------
extern "C" void kernel_launch(void* const* d_in, const int* in_sizes, int n_in,
                              void* d_out, int out_size)
{
    const int*   x    = (const int*)  d_in[0];
    const float* h0_0 = (const float*)d_in[1];
    const float* h0_1 = (const float*)d_in[2];
    const float* emb  = (const float*)d_in[3];
    const float* Wg0  = (const float*)d_in[4];
    const float* bg0  = (const float*)d_in[5];
    const float* Wc0  = (const float*)d_in[6];
    const float* bc0  = (const float*)d_in[7];
    const float* Wg1  = (const float*)d_in[8];
    const float* bg1  = (const float*)d_in[9];
    const float* Wc1  = (const float*)d_in[10];
    const float* bc1  = (const float*)d_in[11];
    float* out = (float*)d_out;

    float *Xg, *Xc, *y0;
    cudaGetSymbolAddress((void**)&Xg, g_Xg);
    cudaGetSymbolAddress((void**)&Xc, g_Xc);
    cudaGetSymbolAddress((void**)&y0, g_y0);

    static int smem_set = 0;
    const int SMEM_BYTES = SMEM_FLOATS * 4;   // 115328
    if (!smem_set) {
        cudaFuncSetAttribute(gru_scan, cudaFuncAttributeMaxDynamicSharedMemorySize, SMEM_BYTES);
        smem_set = 1;
    }

    float* s0_out = out + (size_t)BSz * Uz;
    float* s1_out = s0_out + Bz * Uz;

    // ---------- layer 0 ----------
    sgemm_bias<<<dim3(U2 / 128, BSz / 128), 256>>>(emb, x, Wg0, bg0, Xg, BSz, U2, Ez);
    sgemm_bias<<<dim3(Uz / 128, BSz / 128), 256>>>(emb, x, Wc0, bc0, Xc, BSz, Uz, Ez);
    gru_scan<<<NBLK, NTHR, SMEM_BYTES>>>(
        Wg0 + (size_t)Ez * U2, Wc0 + (size_t)Ez * Uz, Xg, Xc, h0_0, y0, s0_out);

    // ---------- layer 1 ----------
    sgemm_bias<<<dim3(U2 / 128, BSz / 128), 256>>>(y0, nullptr, Wg1, bg1, Xg, BSz, U2, Uz);
    sgemm_bias<<<dim3(Uz / 128, BSz / 128), 256>>>(y0, nullptr, Wc1, bc1, Xc, BSz, Uz, Uz);
    gru_scan<<<NBLK, NTHR, SMEM_BYTES>>>(
        Wg1 + (size_t)Uz * U2, Wc1 + (size_t)Uz * Uz, Xg, Xc, h0_1, out /*y1*/, s1_out);
}